// round 6
// baseline (speedup 1.0000x reference)
#include <cuda_runtime.h>
#include <cstdint>

// Problem constants (fixed by setup_inputs)
#define BS 4
#define NN 1024
#define GD 6
#define CC 256
#define HH 8
#define DH 32
#define MC 64
#define HID 16

#define SKSTRIDE 257   // conflict-free smem stride for the 64x256 K/V tile

// ---------------- scratch (device globals; no allocation allowed) ----------
__device__ int   g_nbhd [BS * NN * MC];     // neighbor indices
__device__ float g_q[BS * NN * CC];
__device__ float g_k[BS * NN * CC];
__device__ float g_v[BS * NN * CC];
__device__ float g_ao[BS * NN * CC];        // attention output before W_out
__device__ unsigned char g_mask[BS * NN];   // normalized mask (0/1), dtype-agnostic

__device__ __forceinline__ float swishf(float x) {
    return x / (1.0f + __expf(-x));
}

// ---------------- Kernel 0: normalize mask regardless of bool/int32 layout -
__global__ void mask_norm_kernel(const unsigned char* __restrict__ raw) {
    __shared__ int flag;
    if (threadIdx.x == 0) flag = 0;
    __syncthreads();
    int local = 0;
    for (int i = threadIdx.x; i < BS * NN; i += 256)
        if ((i & 3) != 0 && raw[i]) local = 1;
    if (local) atomicOr(&flag, 1);
    __syncthreads();
    bool is_bytes = (flag != 0);
    const int* ri = (const int*)raw;
    for (int i = threadIdx.x; i < BS * NN; i += 256)
        g_mask[i] = is_bytes ? (raw[i] != 0 ? 1 : 0) : (ri[i] != 0 ? 1 : 0);
}

// ---------------- Kernel A: float4 pass-through copy of pairwise_g ---------
__global__ void copy_g_kernel(const float4* __restrict__ src,
                              float4* __restrict__ dst, int n4) {
    int i = blockIdx.x * blockDim.x + threadIdx.x;
    if (i < n4) dst[i] = src[i];
}

// ---------------- Kernel B: fused distances + top-64 via radix select ------
__global__ void topk_kernel(const float* __restrict__ g) {
    __shared__ unsigned int skey[NN];
    __shared__ unsigned int hist[256];
    __shared__ unsigned int cum[256];
    __shared__ unsigned int warpsum[8];
    __shared__ unsigned int s_prefix, s_total_lt, s_rt;
    __shared__ int s_bin;
    __shared__ unsigned int c_lt, c_eq;

    int row = blockIdx.x;                    // b*N + i
    int b = row >> 10;
    int t = threadIdx.x;                     // 256 threads
    int lane = t & 31, w = t >> 5;

    const float* base = g + (size_t)row * NN * GD;
    #pragma unroll
    for (int r = 0; r < 4; r++) {
        int e = t + r * 256;
        const float* p = base + e * GD;
        float x0 = p[0], x1 = p[1], x2 = p[2], x3 = p[3], x4 = p[4], x5 = p[5];
        float s = x0*x0 + x1*x1 + x2*x2 + x3*x3 + x4*x4 + x5*x5;
        if (!g_mask[(b << 10) + e]) s = 1e16f;
        skey[e] = __float_as_uint(s);
    }
    if (t == 0) { s_prefix = 0u; s_total_lt = 0u; s_rt = MC; }
    __syncthreads();

    #pragma unroll
    for (int pass = 0; pass < 4; pass++) {
        int shift = 24 - pass * 8;
        unsigned int pmask = (pass == 0) ? 0u : (0xFFFFFFFFu << (shift + 8));
        hist[t] = 0u;
        __syncthreads();
        unsigned int prefix = s_prefix;
        #pragma unroll
        for (int r = 0; r < 4; r++) {
            unsigned int key = skey[t + r * 256];
            if ((key & pmask) == prefix)
                atomicAdd(&hist[(key >> shift) & 0xFFu], 1u);
        }
        __syncthreads();
        unsigned int inc = hist[t];
        #pragma unroll
        for (int o = 1; o < 32; o <<= 1) {
            unsigned int u = __shfl_up_sync(0xFFFFFFFFu, inc, o);
            if (lane >= o) inc += u;
        }
        if (lane == 31) warpsum[w] = inc;
        __syncthreads();
        if (w == 0) {
            unsigned int ws = (lane < 8) ? warpsum[lane] : 0u;
            #pragma unroll
            for (int o = 1; o < 8; o <<= 1) {
                unsigned int u = __shfl_up_sync(0xFFFFFFFFu, ws, o);
                if (lane >= o) ws += u;
            }
            if (lane < 8) warpsum[lane] = ws;
        }
        __syncthreads();
        unsigned int incl = inc + (w > 0 ? warpsum[w - 1] : 0u);
        cum[t] = incl;
        __syncthreads();
        unsigned int rt = s_rt;
        unsigned int prev = (t == 0) ? 0u : cum[t - 1];
        if (incl >= rt && prev < rt) s_bin = t;
        __syncthreads();
        if (t == 0) {
            int bin = s_bin;
            unsigned int cb = (bin == 0) ? 0u : cum[bin - 1];
            s_total_lt += cb;
            s_rt = s_rt - cb;
            s_prefix = s_prefix | ((unsigned int)bin << shift);
        }
        __syncthreads();
    }

    unsigned int T = s_prefix;
    unsigned int total_lt = s_total_lt;
    if (t == 0) { c_lt = 0u; c_eq = 0u; }
    __syncthreads();
    int* outp = g_nbhd + row * MC;
    #pragma unroll
    for (int r = 0; r < 4; r++) {
        int e = t + r * 256;
        unsigned int key = skey[e];
        if (key < T) {
            unsigned int pos = atomicAdd(&c_lt, 1u);
            outp[pos] = e;
        } else if (key == T) {
            unsigned int pe = atomicAdd(&c_eq, 1u);
            unsigned int pos = total_lt + pe;
            if (pos < MC) outp[pos] = e;
        }
    }
}

// ---------------- GEMM 128x64 tile, 8x4 microtile, K=256 -------------------
__device__ __forceinline__ void gemm_tile_128x64(
    const float* __restrict__ A, const float* __restrict__ B,
    const float* __restrict__ bias, float* __restrict__ C,
    int mb, int col0)
{
    __shared__ float As[16][132];
    __shared__ float Bsh[16][64];
    float acc[8][4];
    #pragma unroll
    for (int i = 0; i < 8; i++)
        #pragma unroll
        for (int j = 0; j < 4; j++) acc[i][j] = 0.f;

    int t = threadIdx.x;
    int tm = t >> 4, tn = t & 15;           // tm: 0..15 (8 rows each), tn: 0..15 (4 cols)

    for (int k0 = 0; k0 < CC; k0 += 16) {
        #pragma unroll
        for (int r = 0; r < 2; r++) {
            int idx = t + r * 256;           // 0..511
            int m = idx >> 2, kq = idx & 3;
            float4 a = *(const float4*)(A + (size_t)(mb + m) * CC + k0 + kq * 4);
            As[kq*4+0][m] = a.x; As[kq*4+1][m] = a.y;
            As[kq*4+2][m] = a.z; As[kq*4+3][m] = a.w;
        }
        {
            int kk = t >> 4, n4 = t & 15;
            float4 b4 = *(const float4*)(B + (size_t)(k0 + kk) * CC + col0 + n4 * 4);
            *(float4*)&Bsh[kk][n4 * 4] = b4;
        }
        __syncthreads();
        #pragma unroll
        for (int kk = 0; kk < 16; kk++) {
            float a[8], b[4];
            #pragma unroll
            for (int i = 0; i < 8; i++) a[i] = As[kk][tm * 8 + i];
            #pragma unroll
            for (int j = 0; j < 4; j++) b[j] = Bsh[kk][tn * 4 + j];
            #pragma unroll
            for (int i = 0; i < 8; i++)
                #pragma unroll
                for (int j = 0; j < 4; j++) acc[i][j] += a[i] * b[j];
        }
        __syncthreads();
    }
    #pragma unroll
    for (int i = 0; i < 8; i++)
        #pragma unroll
        for (int j = 0; j < 4; j++)
            C[(size_t)(mb + tm*8 + i) * CC + col0 + tn*4 + j] = acc[i][j] + bias[col0 + tn*4 + j];
}

__global__ void __launch_bounds__(256) qkv_gemm_kernel(
    const float* __restrict__ A,
    const float* __restrict__ Wq, const float* __restrict__ bq,
    const float* __restrict__ Wk, const float* __restrict__ bk,
    const float* __restrict__ Wv, const float* __restrict__ bv)
{
    int mb = blockIdx.x * 128;
    int yb = blockIdx.y;                     // 0..11
    int which = yb >> 2;
    int col0 = (yb & 3) * 64;
    const float* B  = which == 0 ? Wq : (which == 1 ? Wk : Wv);
    const float* bi = which == 0 ? bq : (which == 1 ? bk : bv);
    float* C = which == 0 ? g_q : (which == 1 ? g_k : g_v);
    gemm_tile_128x64(A, B, bi, C, mb, col0);
}

__global__ void __launch_bounds__(256) out_gemm_kernel(
    const float* __restrict__ B, const float* __restrict__ bias,
    float* __restrict__ C)
{
    gemm_tile_128x64(g_ao, B, bias, C, blockIdx.x * 128, blockIdx.y * 64);
}

// ---------------- Kernel D: attention (loc-MLP + feat + softmax + AV) ------
// Dynamic smem: sk[64][257] staging buffer for the gathered K tile, then V.
__global__ void __launch_bounds__(256) attn_kernel(
                            const float* __restrict__ g,
                            const float* __restrict__ lW1, const float* __restrict__ lb1,
                            const float* __restrict__ lW2, const float* __restrict__ lb2,
                            const float* __restrict__ lW3, const float* __restrict__ lb3) {
    __shared__ float sW1[HH * GD * HID];
    __shared__ float sB1[HH * HID];
    __shared__ float sW2[HH * HID * HID];
    __shared__ float sB2[HH * HID];
    __shared__ float sW3[HH * HID];
    __shared__ float sB3[HH];
    __shared__ float sng[MC * 7];
    __shared__ float sq[CC];
    __shared__ float sscore[HH * MC];
    __shared__ float sattn [HH * MC];
    __shared__ int   snidx[MC];
    __shared__ int   snm[MC];
    extern __shared__ float sk[];            // MC * SKSTRIDE floats

    int i = blockIdx.x;
    int b = blockIdx.y;
    int t = threadIdx.x;
    int warp = t >> 5;
    int lane = t & 31;
    int row = b * NN + i;

    for (int x = t; x < HH * GD * HID; x += 256) sW1[x] = lW1[x];
    for (int x = t; x < HH * HID;      x += 256) sB1[x] = lb1[x];
    for (int x = t; x < HH * HID * HID;x += 256) sW2[x] = lW2[x];
    for (int x = t; x < HH * HID;      x += 256) sB2[x] = lb2[x];
    for (int x = t; x < HH * HID;      x += 256) sW3[x] = lW3[x];
    if (t < HH) sB3[t] = lb3[t];

    if (t < MC) {
        int id = g_nbhd[row * MC + t];
        snidx[t] = id;
        snm[t] = g_mask[b * NN + id] != 0 ? 1 : 0;
    }
    sq[t] = g_q[(size_t)row * CC + t];
    __syncthreads();

    // gather neighbor group elements + stage K tile (coalesced 1KB rows)
    for (int x = t; x < MC * GD; x += 256) {
        int m = x / GD, gk = x - m * GD;
        sng[m * 7 + gk] = g[(((size_t)row) * NN + snidx[m]) * GD + gk];
    }
    #pragma unroll
    for (int r = 0; r < MC; r++) {
        sk[r * SKSTRIDE + t] = g_k[((size_t)(b * NN + snidx[r])) * CC + t];
    }
    __syncthreads();

    // ---- location MLP: warp = head, lane handles m=lane and m=lane+32.
    // Layers 2+3 fused (h2[l] used exactly once) to cut register pressure.
    {
        int h = warp;
        float xa[GD], xb[GD];
        #pragma unroll
        for (int gg = 0; gg < GD; gg++) {
            xa[gg] = sng[lane * 7 + gg];
            xb[gg] = sng[(lane + 32) * 7 + gg];
        }
        float h1a[HID], h1b[HID];
        #pragma unroll
        for (int k2 = 0; k2 < HID; k2++) {
            float aa = sB1[h * HID + k2], ab = aa;
            #pragma unroll
            for (int gg = 0; gg < GD; gg++) {
                float w = sW1[h * (GD * HID) + gg * HID + k2];
                aa += xa[gg] * w; ab += xb[gg] * w;
            }
            h1a[k2] = swishf(aa); h1b[k2] = swishf(ab);
        }
        float oa = sB3[h], ob = oa;
        #pragma unroll
        for (int l = 0; l < HID; l++) {
            float aa = sB2[h * HID + l], ab = aa;
            #pragma unroll
            for (int k2 = 0; k2 < HID; k2++) {
                float w = sW2[h * (HID * HID) + k2 * HID + l];
                aa += h1a[k2] * w; ab += h1b[k2] * w;
            }
            float w3 = sW3[h * HID + l];
            oa += swishf(aa) * w3; ob += swishf(ab) * w3;
        }
        // ---- feature scores from staged K (no shuffles, no serialization)
        const float inv = 0.17677669529663687f;  // 1/sqrt(32)
        float fa = 0.f, fb = 0.f;
        #pragma unroll
        for (int d = 0; d < DH; d++) {
            float qd = sq[h * DH + d];
            fa += qd * sk[lane        * SKSTRIDE + h * DH + d];
            fb += qd * sk[(lane + 32) * SKSTRIDE + h * DH + d];
        }
        sscore[h * MC + lane]      = swishf(oa) + fa * inv;
        sscore[h * MC + lane + 32] = swishf(ob) + fb * inv;
    }
    __syncthreads();                          // all warps done reading K tile

    // re-stage buffer with V tile
    #pragma unroll
    for (int r = 0; r < MC; r++) {
        sk[r * SKSTRIDE + t] = g_v[((size_t)(b * NN + snidx[r])) * CC + t];
    }

    // ---- masked softmax over m (per head) — uses only warp-own sscore rows
    {
        int h = warp;
        float s0 = snm[lane]      ? sscore[h * MC + lane]      : -1e38f;
        float s1 = snm[lane + 32] ? sscore[h * MC + lane + 32] : -1e38f;
        float mx = fmaxf(s0, s1);
        #pragma unroll
        for (int o = 16; o > 0; o >>= 1)
            mx = fmaxf(mx, __shfl_xor_sync(0xFFFFFFFFu, mx, o));
        float e0 = __expf(s0 - mx), e1 = __expf(s1 - mx);
        float sm = e0 + e1;
        #pragma unroll
        for (int o = 16; o > 0; o >>= 1)
            sm += __shfl_xor_sync(0xFFFFFFFFu, sm, o);
        float invs = 1.0f / sm;
        sattn[h * MC + lane]      = e0 * invs;
        sattn[h * MC + lane + 32] = e1 * invs;
    }
    __syncthreads();                          // V staged + attn ready

    // ---- weighted V from staged tile: thread t = channel c, head = warp
    {
        float acc = 0.f;
        #pragma unroll
        for (int m = 0; m < MC; m++) {
            acc += sattn[warp * MC + m] * sk[m * SKSTRIDE + t];
        }
        g_ao[(size_t)row * CC + t] = acc;
    }
}

// ---------------- Kernel F: mask -> float tail -----------------------------
__global__ void mask_out_kernel(float* __restrict__ out_m) {
    int t = blockIdx.x * blockDim.x + threadIdx.x;
    if (t < BS * NN) out_m[t] = g_mask[t] ? 1.0f : 0.0f;
}

// ---------------- launch ---------------------------------------------------
extern "C" void kernel_launch(void* const* d_in, const int* in_sizes, int n_in,
                              void* d_out, int out_size) {
    const float*         pg   = (const float*)d_in[0];
    const float*         cf   = (const float*)d_in[1];
    const unsigned char* mask = (const unsigned char*)d_in[2];
    const float* lW1 = (const float*)d_in[3];
    const float* lb1 = (const float*)d_in[4];
    const float* lW2 = (const float*)d_in[5];
    const float* lb2 = (const float*)d_in[6];
    const float* lW3 = (const float*)d_in[7];
    const float* lb3 = (const float*)d_in[8];
    const float* Wq  = (const float*)d_in[9];
    const float* bq  = (const float*)d_in[10];
    const float* Wk  = (const float*)d_in[11];
    const float* bk  = (const float*)d_in[12];
    const float* Win = (const float*)d_in[13];
    const float* bin = (const float*)d_in[14];
    const float* Wout= (const float*)d_in[15];
    const float* bout= (const float*)d_in[16];

    const size_t GSZ = (size_t)BS * NN * NN * GD;   // 25165824
    const size_t OSZ = (size_t)BS * NN * CC;        // 1048576
    const size_t MSZ = (size_t)BS * NN;             // 4096

    float* out = (float*)d_out;
    float* out_g = nullptr;
    float* out_o = out;
    float* out_m = nullptr;
    size_t osz = (size_t)out_size;
    if (osz == GSZ + OSZ + MSZ)      { out_g = out; out_o = out + GSZ; out_m = out + GSZ + OSZ; }
    else if (osz == GSZ + OSZ)       { out_g = out; out_o = out + GSZ; }
    else if (osz == OSZ + MSZ)       { out_o = out; out_m = out + OSZ; }

    static int smem_set = 0;
    const int attn_dyn = MC * SKSTRIDE * sizeof(float);   // 65792 B
    if (!smem_set) {
        cudaFuncSetAttribute(attn_kernel, cudaFuncAttributeMaxDynamicSharedMemorySize, attn_dyn);
        smem_set = 1;
    }

    mask_norm_kernel<<<1, 256>>>(mask);
    if (out_g) {
        int n4 = (int)(GSZ / 4);
        copy_g_kernel<<<(n4 + 255) / 256, 256>>>((const float4*)pg, (float4*)out_g, n4);
    }
    topk_kernel<<<BS * NN, 256>>>(pg);
    qkv_gemm_kernel<<<dim3(BS * NN / 128, 12), 256>>>(cf, Wq, bq, Wk, bk, Win, bin);
    attn_kernel<<<dim3(NN, BS), 256, attn_dyn>>>(pg, lW1, lb1, lW2, lb2, lW3, lb3);
    out_gemm_kernel<<<dim3(BS * NN / 128, CC / 64), 256>>>(Wout, bout, out_o);
    if (out_m) mask_out_kernel<<<(BS * NN + 255) / 256, 256>>>(out_m);
}

// round 7
// speedup vs baseline: 1.5019x; 1.5019x over previous
#include <cuda_runtime.h>
#include <cstdint>

// Problem constants (fixed by setup_inputs)
#define BS 4
#define NN 1024
#define GD 6
#define CC 256
#define HH 8
#define DH 32
#define MC 64
#define HID 16

// ---------------- scratch (device globals; no allocation allowed) ----------
__device__ int   g_nbhd [BS * NN * MC];     // neighbor indices
__device__ float g_q[BS * NN * CC];
__device__ float g_k[BS * NN * CC];
__device__ float g_v[BS * NN * CC];
__device__ float g_ao[BS * NN * CC];        // attention output before W_out
__device__ unsigned char g_mask[BS * NN];   // normalized mask (0/1), dtype-agnostic

__device__ __forceinline__ float swishf(float x) {
    return x / (1.0f + __expf(-x));
}

// ---------------- Kernel 0: normalize mask regardless of bool/int32 layout -
__global__ void mask_norm_kernel(const unsigned char* __restrict__ raw) {
    __shared__ int flag;
    if (threadIdx.x == 0) flag = 0;
    __syncthreads();
    int local = 0;
    for (int i = threadIdx.x; i < BS * NN; i += 256)
        if ((i & 3) != 0 && raw[i]) local = 1;
    if (local) atomicOr(&flag, 1);
    __syncthreads();
    bool is_bytes = (flag != 0);
    const int* ri = (const int*)raw;
    for (int i = threadIdx.x; i < BS * NN; i += 256)
        g_mask[i] = is_bytes ? (raw[i] != 0 ? 1 : 0) : (ri[i] != 0 ? 1 : 0);
}

// ---------------- Kernel B: fused distances + top-64 + pass-through copy ---
// One block per (b,i) row. While computing masked squared distances for the
// radix select, also stream the row's 24KB slice of pairwise_g to out_g
// (eliminates the separate copy kernel's extra 100MB read).
__global__ void topk_kernel(const float* __restrict__ g, float* __restrict__ out_g) {
    __shared__ unsigned int skey[NN];
    __shared__ unsigned int hist[256];
    __shared__ unsigned int cum[256];
    __shared__ unsigned int warpsum[8];
    __shared__ unsigned int s_prefix, s_total_lt, s_rt;
    __shared__ int s_bin;
    __shared__ unsigned int c_lt, c_eq;

    int row = blockIdx.x;                    // b*N + i
    int b = row >> 10;
    int t = threadIdx.x;                     // 256 threads
    int lane = t & 31, w = t >> 5;

    const float2* base2 = (const float2*)(g + (size_t)row * NN * GD);
    float2* out2 = out_g ? (float2*)(out_g + (size_t)row * NN * GD) : nullptr;
    #pragma unroll
    for (int r = 0; r < 4; r++) {
        int e = t + r * 256;
        float2 p0 = base2[e * 3 + 0];
        float2 p1 = base2[e * 3 + 1];
        float2 p2 = base2[e * 3 + 2];
        float s = p0.x*p0.x + p0.y*p0.y + p1.x*p1.x + p1.y*p1.y + p2.x*p2.x + p2.y*p2.y;
        if (!g_mask[(b << 10) + e]) s = 1e16f;
        skey[e] = __float_as_uint(s);
        if (out2) {
            out2[e * 3 + 0] = p0;
            out2[e * 3 + 1] = p1;
            out2[e * 3 + 2] = p2;
        }
    }
    if (t == 0) { s_prefix = 0u; s_total_lt = 0u; s_rt = MC; }
    __syncthreads();

    #pragma unroll
    for (int pass = 0; pass < 4; pass++) {
        int shift = 24 - pass * 8;
        unsigned int pmask = (pass == 0) ? 0u : (0xFFFFFFFFu << (shift + 8));
        hist[t] = 0u;
        __syncthreads();
        unsigned int prefix = s_prefix;
        #pragma unroll
        for (int r = 0; r < 4; r++) {
            unsigned int key = skey[t + r * 256];
            if ((key & pmask) == prefix)
                atomicAdd(&hist[(key >> shift) & 0xFFu], 1u);
        }
        __syncthreads();
        unsigned int inc = hist[t];
        #pragma unroll
        for (int o = 1; o < 32; o <<= 1) {
            unsigned int u = __shfl_up_sync(0xFFFFFFFFu, inc, o);
            if (lane >= o) inc += u;
        }
        if (lane == 31) warpsum[w] = inc;
        __syncthreads();
        if (w == 0) {
            unsigned int ws = (lane < 8) ? warpsum[lane] : 0u;
            #pragma unroll
            for (int o = 1; o < 8; o <<= 1) {
                unsigned int u = __shfl_up_sync(0xFFFFFFFFu, ws, o);
                if (lane >= o) ws += u;
            }
            if (lane < 8) warpsum[lane] = ws;
        }
        __syncthreads();
        unsigned int incl = inc + (w > 0 ? warpsum[w - 1] : 0u);
        cum[t] = incl;
        __syncthreads();
        unsigned int rt = s_rt;
        unsigned int prev = (t == 0) ? 0u : cum[t - 1];
        if (incl >= rt && prev < rt) s_bin = t;
        __syncthreads();
        if (t == 0) {
            int bin = s_bin;
            unsigned int cb = (bin == 0) ? 0u : cum[bin - 1];
            s_total_lt += cb;
            s_rt = s_rt - cb;
            s_prefix = s_prefix | ((unsigned int)bin << shift);
        }
        __syncthreads();
    }

    unsigned int T = s_prefix;
    unsigned int total_lt = s_total_lt;
    if (t == 0) { c_lt = 0u; c_eq = 0u; }
    __syncthreads();
    int* outp = g_nbhd + row * MC;
    #pragma unroll
    for (int r = 0; r < 4; r++) {
        int e = t + r * 256;
        unsigned int key = skey[e];
        if (key < T) {
            unsigned int pos = atomicAdd(&c_lt, 1u);
            outp[pos] = e;
        } else if (key == T) {
            unsigned int pe = atomicAdd(&c_eq, 1u);
            unsigned int pos = total_lt + pe;
            if (pos < MC) outp[pos] = e;
        }
    }
}

// ---------------- GEMM 128x64 tile, 8x4 microtile, K=256 -------------------
__device__ __forceinline__ void gemm_tile_128x64(
    const float* __restrict__ A, const float* __restrict__ B,
    const float* __restrict__ bias, float* __restrict__ C,
    int mb, int col0)
{
    __shared__ float As[16][132];
    __shared__ float Bsh[16][64];
    float acc[8][4];
    #pragma unroll
    for (int i = 0; i < 8; i++)
        #pragma unroll
        for (int j = 0; j < 4; j++) acc[i][j] = 0.f;

    int t = threadIdx.x;
    int tm = t >> 4, tn = t & 15;

    for (int k0 = 0; k0 < CC; k0 += 16) {
        #pragma unroll
        for (int r = 0; r < 2; r++) {
            int idx = t + r * 256;
            int m = idx >> 2, kq = idx & 3;
            float4 a = *(const float4*)(A + (size_t)(mb + m) * CC + k0 + kq * 4);
            As[kq*4+0][m] = a.x; As[kq*4+1][m] = a.y;
            As[kq*4+2][m] = a.z; As[kq*4+3][m] = a.w;
        }
        {
            int kk = t >> 4, n4 = t & 15;
            float4 b4 = *(const float4*)(B + (size_t)(k0 + kk) * CC + col0 + n4 * 4);
            *(float4*)&Bsh[kk][n4 * 4] = b4;
        }
        __syncthreads();
        #pragma unroll
        for (int kk = 0; kk < 16; kk++) {
            float a[8], b[4];
            #pragma unroll
            for (int i = 0; i < 8; i++) a[i] = As[kk][tm * 8 + i];
            #pragma unroll
            for (int j = 0; j < 4; j++) b[j] = Bsh[kk][tn * 4 + j];
            #pragma unroll
            for (int i = 0; i < 8; i++)
                #pragma unroll
                for (int j = 0; j < 4; j++) acc[i][j] += a[i] * b[j];
        }
        __syncthreads();
    }
    #pragma unroll
    for (int i = 0; i < 8; i++)
        #pragma unroll
        for (int j = 0; j < 4; j++)
            C[(size_t)(mb + tm*8 + i) * CC + col0 + tn*4 + j] = acc[i][j] + bias[col0 + tn*4 + j];
}

__global__ void __launch_bounds__(256) qkv_gemm_kernel(
    const float* __restrict__ A,
    const float* __restrict__ Wq, const float* __restrict__ bq,
    const float* __restrict__ Wk, const float* __restrict__ bk,
    const float* __restrict__ Wv, const float* __restrict__ bv)
{
    int mb = blockIdx.x * 128;
    int yb = blockIdx.y;
    int which = yb >> 2;
    int col0 = (yb & 3) * 64;
    const float* B  = which == 0 ? Wq : (which == 1 ? Wk : Wv);
    const float* bi = which == 0 ? bq : (which == 1 ? bk : bv);
    float* C = which == 0 ? g_q : (which == 1 ? g_k : g_v);
    gemm_tile_128x64(A, B, bi, C, mb, col0);
}

__global__ void __launch_bounds__(256) out_gemm_kernel(
    const float* __restrict__ B, const float* __restrict__ bias,
    float* __restrict__ C)
{
    gemm_tile_128x64(g_ao, B, bias, C, blockIdx.x * 128, blockIdx.y * 64);
}

// ---------------- Kernel D: attention (R5 known-good version) --------------
__global__ void attn_kernel(const float* __restrict__ g,
                            const float* __restrict__ lW1, const float* __restrict__ lb1,
                            const float* __restrict__ lW2, const float* __restrict__ lb2,
                            const float* __restrict__ lW3, const float* __restrict__ lb3) {
    __shared__ float sW1[HH * GD * HID];
    __shared__ float sB1[HH * HID];
    __shared__ float sW2[HH * HID * HID];
    __shared__ float sB2[HH * HID];
    __shared__ float sW3[HH * HID];
    __shared__ float sB3[HH];
    __shared__ float sng[MC * 7];
    __shared__ float sq[CC];
    __shared__ float sscore[HH * MC];
    __shared__ float sattn [HH * MC];
    __shared__ int   snidx[MC];
    __shared__ int   snm[MC];

    int i = blockIdx.x;
    int b = blockIdx.y;
    int t = threadIdx.x;
    int warp = t >> 5;
    int lane = t & 31;
    int row = b * NN + i;

    for (int x = t; x < HH * GD * HID; x += 256) sW1[x] = lW1[x];
    for (int x = t; x < HH * HID;      x += 256) sB1[x] = lb1[x];
    for (int x = t; x < HH * HID * HID;x += 256) sW2[x] = lW2[x];
    for (int x = t; x < HH * HID;      x += 256) sB2[x] = lb2[x];
    for (int x = t; x < HH * HID;      x += 256) sW3[x] = lW3[x];
    if (t < HH) sB3[t] = lb3[t];

    if (t < MC) {
        int id = g_nbhd[row * MC + t];
        snidx[t] = id;
        snm[t] = g_mask[b * NN + id] != 0 ? 1 : 0;
    }
    sq[t] = g_q[(size_t)row * CC + t];
    __syncthreads();

    for (int x = t; x < MC * GD; x += 256) {
        int m = x / GD, gk = x - m * GD;
        sng[m * 7 + gk] = g[(((size_t)row) * NN + snidx[m]) * GD + gk];
    }
    __syncthreads();

    // ---- location MLP: warp = head, each lane handles m=lane and m=lane+32
    {
        int h = warp;
        float xa[GD], xb[GD];
        #pragma unroll
        for (int gg = 0; gg < GD; gg++) {
            xa[gg] = sng[lane * 7 + gg];
            xb[gg] = sng[(lane + 32) * 7 + gg];
        }
        float h1a[HID], h1b[HID];
        #pragma unroll
        for (int k2 = 0; k2 < HID; k2++) {
            float aa = sB1[h * HID + k2], ab = aa;
            #pragma unroll
            for (int gg = 0; gg < GD; gg++) {
                float w = sW1[h * (GD * HID) + gg * HID + k2];
                aa += xa[gg] * w; ab += xb[gg] * w;
            }
            h1a[k2] = swishf(aa); h1b[k2] = swishf(ab);
        }
        float h2a[HID], h2b[HID];
        #pragma unroll
        for (int l = 0; l < HID; l++) {
            float aa = sB2[h * HID + l], ab = aa;
            #pragma unroll
            for (int k2 = 0; k2 < HID; k2++) {
                float w = sW2[h * (HID * HID) + k2 * HID + l];
                aa += h1a[k2] * w; ab += h1b[k2] * w;
            }
            h2a[l] = swishf(aa); h2b[l] = swishf(ab);
        }
        float oa = sB3[h], ob = oa;
        #pragma unroll
        for (int k2 = 0; k2 < HID; k2++) {
            float w = sW3[h * HID + k2];
            oa += h2a[k2] * w; ob += h2b[k2] * w;
        }
        sscore[h * MC + lane]      = swishf(oa);
        sscore[h * MC + lane + 32] = swishf(ob);
    }
    __syncwarp();

    // ---- feature scores: warp = head, lanes over dh, reduce per m
    {
        int h = warp;
        const float inv = 0.17677669529663687f;  // 1/sqrt(32)
        float qv = sq[h * DH + lane];
        #pragma unroll 4
        for (int m = 0; m < MC; m++) {
            int id = snidx[m];
            float kv = g_k[((size_t)(b * NN + id)) * CC + h * DH + lane];
            float s = qv * kv;
            s += __shfl_xor_sync(0xFFFFFFFFu, s, 16);
            s += __shfl_xor_sync(0xFFFFFFFFu, s, 8);
            s += __shfl_xor_sync(0xFFFFFFFFu, s, 4);
            s += __shfl_xor_sync(0xFFFFFFFFu, s, 2);
            s += __shfl_xor_sync(0xFFFFFFFFu, s, 1);
            if (lane == 0) sscore[h * MC + m] += s * inv;
        }
    }
    __syncwarp();

    // ---- masked softmax over m (per head)
    {
        int h = warp;
        float s0 = snm[lane]      ? sscore[h * MC + lane]      : -1e38f;
        float s1 = snm[lane + 32] ? sscore[h * MC + lane + 32] : -1e38f;
        float mx = fmaxf(s0, s1);
        #pragma unroll
        for (int o = 16; o > 0; o >>= 1)
            mx = fmaxf(mx, __shfl_xor_sync(0xFFFFFFFFu, mx, o));
        float e0 = __expf(s0 - mx), e1 = __expf(s1 - mx);
        float sm = e0 + e1;
        #pragma unroll
        for (int o = 16; o > 0; o >>= 1)
            sm += __shfl_xor_sync(0xFFFFFFFFu, sm, o);
        float invs = 1.0f / sm;
        sattn[h * MC + lane]      = e0 * invs;
        sattn[h * MC + lane + 32] = e1 * invs;
    }
    __syncthreads();

    // ---- weighted V accumulation: thread = (head=warp, d=lane)
    {
        float acc = 0.f;
        #pragma unroll 8
        for (int m = 0; m < MC; m++) {
            int id = snidx[m];
            acc += sattn[warp * MC + m] *
                   g_v[((size_t)(b * NN + id)) * CC + warp * DH + lane];
        }
        g_ao[(size_t)row * CC + t] = acc;
    }
}

// ---------------- Kernel F: mask -> float tail -----------------------------
__global__ void mask_out_kernel(float* __restrict__ out_m) {
    int t = blockIdx.x * blockDim.x + threadIdx.x;
    if (t < BS * NN) out_m[t] = g_mask[t] ? 1.0f : 0.0f;
}

// ---------------- launch ---------------------------------------------------
extern "C" void kernel_launch(void* const* d_in, const int* in_sizes, int n_in,
                              void* d_out, int out_size) {
    const float*         pg   = (const float*)d_in[0];
    const float*         cf   = (const float*)d_in[1];
    const unsigned char* mask = (const unsigned char*)d_in[2];
    const float* lW1 = (const float*)d_in[3];
    const float* lb1 = (const float*)d_in[4];
    const float* lW2 = (const float*)d_in[5];
    const float* lb2 = (const float*)d_in[6];
    const float* lW3 = (const float*)d_in[7];
    const float* lb3 = (const float*)d_in[8];
    const float* Wq  = (const float*)d_in[9];
    const float* bq  = (const float*)d_in[10];
    const float* Wk  = (const float*)d_in[11];
    const float* bk  = (const float*)d_in[12];
    const float* Win = (const float*)d_in[13];
    const float* bin = (const float*)d_in[14];
    const float* Wout= (const float*)d_in[15];
    const float* bout= (const float*)d_in[16];

    const size_t GSZ = (size_t)BS * NN * NN * GD;   // 25165824
    const size_t OSZ = (size_t)BS * NN * CC;        // 1048576
    const size_t MSZ = (size_t)BS * NN;             // 4096

    float* out = (float*)d_out;
    float* out_g = nullptr;
    float* out_o = out;
    float* out_m = nullptr;
    size_t osz = (size_t)out_size;
    if (osz == GSZ + OSZ + MSZ)      { out_g = out; out_o = out + GSZ; out_m = out + GSZ + OSZ; }
    else if (osz == GSZ + OSZ)       { out_g = out; out_o = out + GSZ; }
    else if (osz == OSZ + MSZ)       { out_o = out; out_m = out + OSZ; }

    mask_norm_kernel<<<1, 256>>>(mask);
    topk_kernel<<<BS * NN, 256>>>(pg, out_g);
    qkv_gemm_kernel<<<dim3(BS * NN / 128, 12), 256>>>(cf, Wq, bq, Wk, bk, Win, bin);
    attn_kernel<<<dim3(NN, BS), 256>>>(pg, lW1, lb1, lW2, lb2, lW3, lb3);
    out_gemm_kernel<<<dim3(BS * NN / 128, CC / 64), 256>>>(Wout, bout, out_o);
    if (out_m) mask_out_kernel<<<(BS * NN + 255) / 256, 256>>>(out_m);
}

// round 8
// speedup vs baseline: 1.8419x; 1.2264x over previous
#include <cuda_runtime.h>
#include <cstdint>

// Problem constants (fixed by setup_inputs)
#define BS 4
#define NN 1024
#define GD 6
#define CC 256
#define HH 8
#define DH 32
#define MC 64
#define HID 16

// ---------------- scratch (device globals; no allocation allowed) ----------
__device__ int   g_nbhd [BS * NN * MC];     // neighbor indices
__device__ float g_q[BS * NN * CC];
__device__ float g_k[BS * NN * CC];
__device__ float g_v[BS * NN * CC];
__device__ float g_ao[BS * NN * CC];        // attention output before W_out
__device__ float g_attn[BS * NN * HH * MC]; // softmaxed attention weights
__device__ unsigned char g_mask[BS * NN];   // normalized mask (0/1)

__device__ __forceinline__ float swishf(float x) {
    return x / (1.0f + __expf(-x));
}

// ---------------- Kernel 0: normalize mask regardless of bool/int32 layout -
__global__ void mask_norm_kernel(const unsigned char* __restrict__ raw) {
    __shared__ int flag;
    if (threadIdx.x == 0) flag = 0;
    __syncthreads();
    int local = 0;
    for (int i = threadIdx.x; i < BS * NN; i += 256)
        if ((i & 3) != 0 && raw[i]) local = 1;
    if (local) atomicOr(&flag, 1);
    __syncthreads();
    bool is_bytes = (flag != 0);
    const int* ri = (const int*)raw;
    for (int i = threadIdx.x; i < BS * NN; i += 256)
        g_mask[i] = is_bytes ? (raw[i] != 0 ? 1 : 0) : (ri[i] != 0 ? 1 : 0);
}

// ---------------- Kernel B: fused distances + top-64 + pass-through copy ---
__global__ void topk_kernel(const float* __restrict__ g, float* __restrict__ out_g) {
    __shared__ unsigned int skey[NN];
    __shared__ unsigned int hist[256];
    __shared__ unsigned int cum[256];
    __shared__ unsigned int warpsum[8];
    __shared__ unsigned int s_prefix, s_total_lt, s_rt;
    __shared__ int s_bin;
    __shared__ unsigned int c_lt, c_eq;

    int row = blockIdx.x;                    // b*N + i
    int b = row >> 10;
    int t = threadIdx.x;                     // 256 threads
    int lane = t & 31, w = t >> 5;

    const float2* base2 = (const float2*)(g + (size_t)row * NN * GD);
    float2* out2 = out_g ? (float2*)(out_g + (size_t)row * NN * GD) : nullptr;
    #pragma unroll
    for (int r = 0; r < 4; r++) {
        int e = t + r * 256;
        float2 p0 = base2[e * 3 + 0];
        float2 p1 = base2[e * 3 + 1];
        float2 p2 = base2[e * 3 + 2];
        float s = p0.x*p0.x + p0.y*p0.y + p1.x*p1.x + p1.y*p1.y + p2.x*p2.x + p2.y*p2.y;
        if (!g_mask[(b << 10) + e]) s = 1e16f;
        skey[e] = __float_as_uint(s);
        if (out2) {
            out2[e * 3 + 0] = p0;
            out2[e * 3 + 1] = p1;
            out2[e * 3 + 2] = p2;
        }
    }
    if (t == 0) { s_prefix = 0u; s_total_lt = 0u; s_rt = MC; }
    __syncthreads();

    #pragma unroll
    for (int pass = 0; pass < 4; pass++) {
        int shift = 24 - pass * 8;
        unsigned int pmask = (pass == 0) ? 0u : (0xFFFFFFFFu << (shift + 8));
        hist[t] = 0u;
        __syncthreads();
        unsigned int prefix = s_prefix;
        #pragma unroll
        for (int r = 0; r < 4; r++) {
            unsigned int key = skey[t + r * 256];
            if ((key & pmask) == prefix)
                atomicAdd(&hist[(key >> shift) & 0xFFu], 1u);
        }
        __syncthreads();
        unsigned int inc = hist[t];
        #pragma unroll
        for (int o = 1; o < 32; o <<= 1) {
            unsigned int u = __shfl_up_sync(0xFFFFFFFFu, inc, o);
            if (lane >= o) inc += u;
        }
        if (lane == 31) warpsum[w] = inc;
        __syncthreads();
        if (w == 0) {
            unsigned int ws = (lane < 8) ? warpsum[lane] : 0u;
            #pragma unroll
            for (int o = 1; o < 8; o <<= 1) {
                unsigned int u = __shfl_up_sync(0xFFFFFFFFu, ws, o);
                if (lane >= o) ws += u;
            }
            if (lane < 8) warpsum[lane] = ws;
        }
        __syncthreads();
        unsigned int incl = inc + (w > 0 ? warpsum[w - 1] : 0u);
        cum[t] = incl;
        __syncthreads();
        unsigned int rt = s_rt;
        unsigned int prev = (t == 0) ? 0u : cum[t - 1];
        if (incl >= rt && prev < rt) s_bin = t;
        __syncthreads();
        if (t == 0) {
            int bin = s_bin;
            unsigned int cb = (bin == 0) ? 0u : cum[bin - 1];
            s_total_lt += cb;
            s_rt = s_rt - cb;
            s_prefix = s_prefix | ((unsigned int)bin << shift);
        }
        __syncthreads();
    }

    unsigned int T = s_prefix;
    unsigned int total_lt = s_total_lt;
    if (t == 0) { c_lt = 0u; c_eq = 0u; }
    __syncthreads();
    int* outp = g_nbhd + row * MC;
    #pragma unroll
    for (int r = 0; r < 4; r++) {
        int e = t + r * 256;
        unsigned int key = skey[e];
        if (key < T) {
            unsigned int pos = atomicAdd(&c_lt, 1u);
            outp[pos] = e;
        } else if (key == T) {
            unsigned int pe = atomicAdd(&c_eq, 1u);
            unsigned int pos = total_lt + pe;
            if (pos < MC) outp[pos] = e;
        }
    }
}

// ---------------- GEMM 128x64 tile, 8x4 microtile, K=256 -------------------
__device__ __forceinline__ void gemm_tile_128x64(
    const float* __restrict__ A, const float* __restrict__ B,
    const float* __restrict__ bias, float* __restrict__ C,
    int mb, int col0)
{
    __shared__ float As[16][132];
    __shared__ float Bsh[16][64];
    float acc[8][4];
    #pragma unroll
    for (int i = 0; i < 8; i++)
        #pragma unroll
        for (int j = 0; j < 4; j++) acc[i][j] = 0.f;

    int t = threadIdx.x;
    int tm = t >> 4, tn = t & 15;

    for (int k0 = 0; k0 < CC; k0 += 16) {
        #pragma unroll
        for (int r = 0; r < 2; r++) {
            int idx = t + r * 256;
            int m = idx >> 2, kq = idx & 3;
            float4 a = *(const float4*)(A + (size_t)(mb + m) * CC + k0 + kq * 4);
            As[kq*4+0][m] = a.x; As[kq*4+1][m] = a.y;
            As[kq*4+2][m] = a.z; As[kq*4+3][m] = a.w;
        }
        {
            int kk = t >> 4, n4 = t & 15;
            float4 b4 = *(const float4*)(B + (size_t)(k0 + kk) * CC + col0 + n4 * 4);
            *(float4*)&Bsh[kk][n4 * 4] = b4;
        }
        __syncthreads();
        #pragma unroll
        for (int kk = 0; kk < 16; kk++) {
            float a[8], b[4];
            #pragma unroll
            for (int i = 0; i < 8; i++) a[i] = As[kk][tm * 8 + i];
            #pragma unroll
            for (int j = 0; j < 4; j++) b[j] = Bsh[kk][tn * 4 + j];
            #pragma unroll
            for (int i = 0; i < 8; i++)
                #pragma unroll
                for (int j = 0; j < 4; j++) acc[i][j] += a[i] * b[j];
        }
        __syncthreads();
    }
    #pragma unroll
    for (int i = 0; i < 8; i++)
        #pragma unroll
        for (int j = 0; j < 4; j++)
            C[(size_t)(mb + tm*8 + i) * CC + col0 + tn*4 + j] = acc[i][j] + bias[col0 + tn*4 + j];
}

__global__ void __launch_bounds__(256) qkv_gemm_kernel(
    const float* __restrict__ A,
    const float* __restrict__ Wq, const float* __restrict__ bq,
    const float* __restrict__ Wk, const float* __restrict__ bk,
    const float* __restrict__ Wv, const float* __restrict__ bv)
{
    int mb = blockIdx.x * 128;
    int yb = blockIdx.y;
    int which = yb >> 2;
    int col0 = (yb & 3) * 64;
    const float* B  = which == 0 ? Wq : (which == 1 ? Wk : Wv);
    const float* bi = which == 0 ? bq : (which == 1 ? bk : bv);
    float* C = which == 0 ? g_q : (which == 1 ? g_k : g_v);
    gemm_tile_128x64(A, B, bi, C, mb, col0);
}

__global__ void __launch_bounds__(256) out_gemm_kernel(
    const float* __restrict__ B, const float* __restrict__ bias,
    float* __restrict__ C)
{
    gemm_tile_128x64(g_ao, B, bias, C, blockIdx.x * 128, blockIdx.y * 64);
}

// ---------------- Kernel D1: loc-MLP + feature scores + softmax ------------
// thread t handles m = t&63, heads hbase=t>>6 and hbase+4. No shuffles in the
// score phase; feature dot = 8 independent float4 LDGs per (m,h).
__global__ void __launch_bounds__(256) score_kernel(
                            const float* __restrict__ g,
                            const float* __restrict__ lW1, const float* __restrict__ lb1,
                            const float* __restrict__ lW2, const float* __restrict__ lb2,
                            const float* __restrict__ lW3, const float* __restrict__ lb3) {
    __shared__ float sW1[HH * GD * HID];
    __shared__ float sB1[HH * HID];
    __shared__ float sW2[HH * HID * HID];
    __shared__ float sB2[HH * HID];
    __shared__ float sW3[HH * HID];
    __shared__ float sB3[HH];
    __shared__ float sng[MC * 7];
    __shared__ float sq[CC];
    __shared__ float sscore[HH * MC];
    __shared__ int   snidx[MC];
    __shared__ int   snm[MC];

    int i = blockIdx.x;
    int b = blockIdx.y;
    int t = threadIdx.x;
    int row = b * NN + i;

    for (int x = t; x < HH * GD * HID; x += 256) sW1[x] = lW1[x];
    for (int x = t; x < HH * HID;      x += 256) sB1[x] = lb1[x];
    for (int x = t; x < HH * HID * HID;x += 256) sW2[x] = lW2[x];
    for (int x = t; x < HH * HID;      x += 256) sB2[x] = lb2[x];
    for (int x = t; x < HH * HID;      x += 256) sW3[x] = lW3[x];
    if (t < HH) sB3[t] = lb3[t];

    if (t < MC) {
        int id = g_nbhd[row * MC + t];
        snidx[t] = id;
        snm[t] = g_mask[b * NN + id] != 0 ? 1 : 0;
    }
    sq[t] = g_q[(size_t)row * CC + t];
    __syncthreads();

    for (int x = t; x < MC * GD; x += 256) {
        int m = x / GD, gk = x - m * GD;
        sng[m * 7 + gk] = g[(((size_t)row) * NN + snidx[m]) * GD + gk];
    }
    __syncthreads();

    int m = t & 63;
    int hbase = t >> 6;                       // 0..3
    int id = snidx[m];
    const float* krow = g_k + ((size_t)(b * NN + id)) * CC;
    float x[GD];
    #pragma unroll
    for (int gg = 0; gg < GD; gg++) x[gg] = sng[m * 7 + gg];
    const float inv = 0.17677669529663687f;   // 1/sqrt(32)

    #pragma unroll
    for (int p = 0; p < 2; p++) {
        int h = hbase + p * 4;
        // layer 1
        float h1[HID];
        #pragma unroll
        for (int k2 = 0; k2 < HID; k2++) {
            float aa = sB1[h * HID + k2];
            #pragma unroll
            for (int gg = 0; gg < GD; gg++)
                aa += x[gg] * sW1[h * (GD * HID) + gg * HID + k2];
            h1[k2] = swishf(aa);
        }
        // layers 2+3 fused
        float o = sB3[h];
        #pragma unroll
        for (int l = 0; l < HID; l++) {
            float aa = sB2[h * HID + l];
            #pragma unroll
            for (int k2 = 0; k2 < HID; k2++)
                aa += h1[k2] * sW2[h * (HID * HID) + k2 * HID + l];
            o += swishf(aa) * sW3[h * HID + l];
        }
        // feature dot: 8 float4 loads, no shuffles
        const float4* k4 = (const float4*)(krow + h * DH);
        const float4* q4 = (const float4*)(sq + h * DH);
        float f = 0.f;
        #pragma unroll
        for (int j = 0; j < 8; j++) {
            float4 kv = k4[j];
            float4 qv = q4[j];
            f += kv.x*qv.x + kv.y*qv.y + kv.z*qv.z + kv.w*qv.w;
        }
        sscore[h * MC + m] = swishf(o) + f * inv;
    }
    __syncthreads();

    // ---- masked softmax over m: warp w = head w
    {
        int warp = t >> 5, lane = t & 31;
        float s0 = snm[lane]      ? sscore[warp * MC + lane]      : -1e38f;
        float s1 = snm[lane + 32] ? sscore[warp * MC + lane + 32] : -1e38f;
        float mx = fmaxf(s0, s1);
        #pragma unroll
        for (int o = 16; o > 0; o >>= 1)
            mx = fmaxf(mx, __shfl_xor_sync(0xFFFFFFFFu, mx, o));
        float e0 = __expf(s0 - mx), e1 = __expf(s1 - mx);
        float sm = e0 + e1;
        #pragma unroll
        for (int o = 16; o > 0; o >>= 1)
            sm += __shfl_xor_sync(0xFFFFFFFFu, sm, o);
        float invs = 1.0f / sm;
        float* arow = g_attn + (size_t)row * (HH * MC) + warp * MC;
        arow[lane]      = e0 * invs;
        arow[lane + 32] = e1 * invs;
    }
}

// ---------------- Kernel D2: AV accumulation (high occupancy) --------------
__global__ void __launch_bounds__(256) av_kernel() {
    __shared__ float sattn[HH * MC];
    __shared__ int   snidx[MC];
    int i = blockIdx.x;
    int b = blockIdx.y;
    int t = threadIdx.x;
    int row = b * NN + i;
    int warp = t >> 5;                        // = head for channel t

    if (t < MC) snidx[t] = g_nbhd[row * MC + t];
    sattn[t]       = g_attn[(size_t)row * (HH * MC) + t];
    sattn[t + 256] = g_attn[(size_t)row * (HH * MC) + t + 256];
    __syncthreads();

    float acc = 0.f;
    #pragma unroll 8
    for (int m = 0; m < MC; m++) {
        int id = snidx[m];
        acc += sattn[warp * MC + m] * g_v[((size_t)(b * NN + id)) * CC + t];
    }
    g_ao[(size_t)row * CC + t] = acc;
}

// ---------------- Kernel F: mask -> float tail -----------------------------
__global__ void mask_out_kernel(float* __restrict__ out_m) {
    int t = blockIdx.x * blockDim.x + threadIdx.x;
    if (t < BS * NN) out_m[t] = g_mask[t] ? 1.0f : 0.0f;
}

// ---------------- launch ---------------------------------------------------
extern "C" void kernel_launch(void* const* d_in, const int* in_sizes, int n_in,
                              void* d_out, int out_size) {
    const float*         pg   = (const float*)d_in[0];
    const float*         cf   = (const float*)d_in[1];
    const unsigned char* mask = (const unsigned char*)d_in[2];
    const float* lW1 = (const float*)d_in[3];
    const float* lb1 = (const float*)d_in[4];
    const float* lW2 = (const float*)d_in[5];
    const float* lb2 = (const float*)d_in[6];
    const float* lW3 = (const float*)d_in[7];
    const float* lb3 = (const float*)d_in[8];
    const float* Wq  = (const float*)d_in[9];
    const float* bq  = (const float*)d_in[10];
    const float* Wk  = (const float*)d_in[11];
    const float* bk  = (const float*)d_in[12];
    const float* Win = (const float*)d_in[13];
    const float* bin = (const float*)d_in[14];
    const float* Wout= (const float*)d_in[15];
    const float* bout= (const float*)d_in[16];

    const size_t GSZ = (size_t)BS * NN * NN * GD;   // 25165824
    const size_t OSZ = (size_t)BS * NN * CC;        // 1048576
    const size_t MSZ = (size_t)BS * NN;             // 4096

    float* out = (float*)d_out;
    float* out_g = nullptr;
    float* out_o = out;
    float* out_m = nullptr;
    size_t osz = (size_t)out_size;
    if (osz == GSZ + OSZ + MSZ)      { out_g = out; out_o = out + GSZ; out_m = out + GSZ + OSZ; }
    else if (osz == GSZ + OSZ)       { out_g = out; out_o = out + GSZ; }
    else if (osz == OSZ + MSZ)       { out_o = out; out_m = out + OSZ; }

    mask_norm_kernel<<<1, 256>>>(mask);
    topk_kernel<<<BS * NN, 256>>>(pg, out_g);
    qkv_gemm_kernel<<<dim3(BS * NN / 128, 12), 256>>>(cf, Wq, bq, Wk, bk, Win, bin);
    score_kernel<<<dim3(NN, BS), 256>>>(pg, lW1, lb1, lW2, lb2, lW3, lb3);
    av_kernel<<<dim3(NN, BS), 256>>>();
    out_gemm_kernel<<<dim3(BS * NN / 128, CC / 64), 256>>>(Wout, bout, out_o);
    if (out_m) mask_out_kernel<<<(BS * NN + 255) / 256, 256>>>(out_m);
}